// round 2
// baseline (speedup 1.0000x reference)
#include <cuda_runtime.h>
#include <math.h>

#define T_TOK   4096        // B*N tokens
#define C_DIM   1024
#define FF_DIM  4096
#define E_NUM   8
#define TOPK    2
#define ROWS    (T_TOK*TOPK)

// ---------------- scratch (static device globals; no allocation) ----------------
__device__ int   g_counts[E_NUM];
__device__ int   g_offsets[E_NUM + 1];
__device__ int   g_cursor[E_NUM];
__device__ int   g_top_idx[T_TOK * TOPK];
__device__ float g_top_w[T_TOK * TOPK];
__device__ int   g_rowtok[ROWS];        // row -> token
__device__ float g_rowgate[ROWS];       // row -> gate weight
__device__ int   g_tokrow[ROWS];        // (token,k) -> row
__device__ float g_h[(size_t)ROWS * FF_DIM];   // 134 MB intermediate
__device__ float g_y[(size_t)ROWS * C_DIM];    // 33.5 MB per-row outputs

// ---------------- kernels ----------------
__global__ void zero_kernel() {
    if (threadIdx.x < E_NUM) g_counts[threadIdx.x] = 0;
}

// one warp per token: 8 router logits, softmax, top-2
__global__ void router_kernel(const float* __restrict__ x,
                              const float* __restrict__ rw) {
    int gtid = blockIdx.x * blockDim.x + threadIdx.x;
    int t    = gtid >> 5;
    int lane = threadIdx.x & 31;
    if (t >= T_TOK) return;

    const float4* xr4 = (const float4*)(x + (size_t)t * C_DIM);
    const float4* rw4 = (const float4*)rw;

    float acc[E_NUM];
#pragma unroll
    for (int e = 0; e < E_NUM; e++) acc[e] = 0.f;

    for (int c4 = lane; c4 < C_DIM / 4; c4 += 32) {
        float4 xv = xr4[c4];
#pragma unroll
        for (int e = 0; e < E_NUM; e++) {
            float4 wv = rw4[e * (C_DIM / 4) + c4];
            acc[e] += xv.x * wv.x + xv.y * wv.y + xv.z * wv.z + xv.w * wv.w;
        }
    }
#pragma unroll
    for (int e = 0; e < E_NUM; e++)
#pragma unroll
        for (int o = 16; o; o >>= 1)
            acc[e] += __shfl_xor_sync(0xFFFFFFFFu, acc[e], o);

    if (lane == 0) {
        float m = acc[0];
#pragma unroll
        for (int e = 1; e < E_NUM; e++) m = fmaxf(m, acc[e]);
        float p[E_NUM], Z = 0.f;
#pragma unroll
        for (int e = 0; e < E_NUM; e++) { p[e] = expf(acc[e] - m); Z += p[e]; }
#pragma unroll
        for (int e = 0; e < E_NUM; e++) p[e] /= Z;

        int i0 = 0;
#pragma unroll
        for (int e = 1; e < E_NUM; e++) if (p[e] > p[i0]) i0 = e;
        int i1 = (i0 == 0) ? 1 : 0;
#pragma unroll
        for (int e = 0; e < E_NUM; e++)
            if (e != i0 && p[e] > p[i1]) i1 = e;

        float s  = p[i0] + p[i1] + 1e-9f;
        g_top_idx[2 * t + 0] = i0;  g_top_w[2 * t + 0] = p[i0] / s;
        g_top_idx[2 * t + 1] = i1;  g_top_w[2 * t + 1] = p[i1] / s;
        atomicAdd(&g_counts[i0], 1);
        atomicAdd(&g_counts[i1], 1);
    }
}

__global__ void scan_kernel() {
    if (threadIdx.x == 0) {
        int o = 0;
        for (int e = 0; e < E_NUM; e++) {
            g_offsets[e] = o;
            g_cursor[e]  = o;
            o += g_counts[e];
        }
        g_offsets[E_NUM] = o;
    }
}

__global__ void scatter_kernel() {
    int t = blockIdx.x * blockDim.x + threadIdx.x;
    if (t >= T_TOK) return;
#pragma unroll
    for (int k = 0; k < TOPK; k++) {
        int e   = g_top_idx[2 * t + k];
        int row = atomicAdd(&g_cursor[e], 1);
        g_rowtok[row]      = t;
        g_rowgate[row]     = g_top_w[2 * t + k];
        g_tokrow[2 * t + k] = row;
    }
}

// GEMM1: H[r,f] = gelu( X[tok(r),:] . W1[e][f,:] + b1[e][f] )
// tiles 128x128, BK=8, 256 threads, 8x8 per thread
__global__ void __launch_bounds__(256) gemm1_kernel(const float* __restrict__ x,
                                                    const float* __restrict__ w1,
                                                    const float* __restrict__ b1) {
    int e      = blockIdx.z;
    int rows_e = g_counts[e];
    int m0     = blockIdx.y * 128;
    if (m0 >= rows_e) return;
    int n0   = blockIdx.x * 128;
    int base = g_offsets[e];

    __shared__ float As[8][128];
    __shared__ float Bs[8][128];

    int tid  = threadIdx.x;
    int arow = tid >> 1;            // 0..127
    int acol = (tid & 1) * 4;       // 0 or 4

    int lr = m0 + arow;
    const float* aptr = nullptr;
    if (lr < rows_e)
        aptr = x + (size_t)g_rowtok[base + lr] * C_DIM + acol;
    const float* bptr = w1 + (size_t)e * FF_DIM * C_DIM
                           + (size_t)(n0 + arow) * C_DIM + acol;

    int tx = tid & 15, ty = tid >> 4;
    float acc[8][8];
#pragma unroll
    for (int i = 0; i < 8; i++)
#pragma unroll
        for (int j = 0; j < 8; j++) acc[i][j] = 0.f;

    for (int kt = 0; kt < C_DIM; kt += 8) {
        float4 av = aptr ? *(const float4*)(aptr + kt) : make_float4(0.f, 0.f, 0.f, 0.f);
        float4 bv = *(const float4*)(bptr + kt);
        __syncthreads();
        As[acol + 0][arow] = av.x; As[acol + 1][arow] = av.y;
        As[acol + 2][arow] = av.z; As[acol + 3][arow] = av.w;
        Bs[acol + 0][arow] = bv.x; Bs[acol + 1][arow] = bv.y;
        Bs[acol + 2][arow] = bv.z; Bs[acol + 3][arow] = bv.w;
        __syncthreads();
#pragma unroll
        for (int k = 0; k < 8; k++) {
            float a[8], b[8];
            *(float4*)(a)     = *(const float4*)&As[k][ty * 8];
            *(float4*)(a + 4) = *(const float4*)&As[k][ty * 8 + 4];
            *(float4*)(b)     = *(const float4*)&Bs[k][tx * 8];
            *(float4*)(b + 4) = *(const float4*)&Bs[k][tx * 8 + 4];
#pragma unroll
            for (int i = 0; i < 8; i++)
#pragma unroll
                for (int j = 0; j < 8; j++)
                    acc[i][j] += a[i] * b[j];
        }
    }

#pragma unroll
    for (int i = 0; i < 8; i++) {
        int r = m0 + ty * 8 + i;
        if (r < rows_e) {
            size_t grow = (size_t)(base + r) * FF_DIM;
#pragma unroll
            for (int j = 0; j < 8; j++) {
                int f   = n0 + tx * 8 + j;
                float h = acc[i][j] + b1[e * FF_DIM + f];
                h = 0.5f * h * (1.f + erff(h * 0.70710678118654752f));
                g_h[grow + f] = h;
            }
        }
    }
}

// GEMM2: Y[r,c] = ( H[r,:] . W2[e][c,:] + b2[e][c] ) * gate[r]
__global__ void __launch_bounds__(256) gemm2_kernel(const float* __restrict__ w2,
                                                    const float* __restrict__ b2) {
    int e      = blockIdx.z;
    int rows_e = g_counts[e];
    int m0     = blockIdx.y * 128;
    if (m0 >= rows_e) return;
    int n0   = blockIdx.x * 128;
    int base = g_offsets[e];

    __shared__ float As[8][128];
    __shared__ float Bs[8][128];

    int tid  = threadIdx.x;
    int arow = tid >> 1;
    int acol = (tid & 1) * 4;

    int lr = m0 + arow;
    const float* aptr = nullptr;
    if (lr < rows_e)
        aptr = g_h + (size_t)(base + lr) * FF_DIM + acol;
    const float* bptr = w2 + (size_t)e * C_DIM * FF_DIM
                           + (size_t)(n0 + arow) * FF_DIM + acol;

    int tx = tid & 15, ty = tid >> 4;
    float acc[8][8];
#pragma unroll
    for (int i = 0; i < 8; i++)
#pragma unroll
        for (int j = 0; j < 8; j++) acc[i][j] = 0.f;

    for (int kt = 0; kt < FF_DIM; kt += 8) {
        float4 av = aptr ? *(const float4*)(aptr + kt) : make_float4(0.f, 0.f, 0.f, 0.f);
        float4 bv = *(const float4*)(bptr + kt);
        __syncthreads();
        As[acol + 0][arow] = av.x; As[acol + 1][arow] = av.y;
        As[acol + 2][arow] = av.z; As[acol + 3][arow] = av.w;
        Bs[acol + 0][arow] = bv.x; Bs[acol + 1][arow] = bv.y;
        Bs[acol + 2][arow] = bv.z; Bs[acol + 3][arow] = bv.w;
        __syncthreads();
#pragma unroll
        for (int k = 0; k < 8; k++) {
            float a[8], b[8];
            *(float4*)(a)     = *(const float4*)&As[k][ty * 8];
            *(float4*)(a + 4) = *(const float4*)&As[k][ty * 8 + 4];
            *(float4*)(b)     = *(const float4*)&Bs[k][tx * 8];
            *(float4*)(b + 4) = *(const float4*)&Bs[k][tx * 8 + 4];
#pragma unroll
            for (int i = 0; i < 8; i++)
#pragma unroll
                for (int j = 0; j < 8; j++)
                    acc[i][j] += a[i] * b[j];
        }
    }

#pragma unroll
    for (int i = 0; i < 8; i++) {
        int r = m0 + ty * 8 + i;
        if (r < rows_e) {
            float gate  = g_rowgate[base + r];
            size_t grow = (size_t)(base + r) * C_DIM;
#pragma unroll
            for (int j = 0; j < 8; j++) {
                int c = n0 + tx * 8 + j;
                g_y[grow + c] = (acc[i][j] + b2[e * C_DIM + c]) * gate;
            }
        }
    }
}

// out[t] = y[row(t,0)] + y[row(t,1)]   (gates already applied; deterministic)
__global__ void combine_kernel(float* __restrict__ out) {
    int i = blockIdx.x * blockDim.x + threadIdx.x;   // over T*C/4
    if (i >= T_TOK * (C_DIM / 4)) return;
    int t  = i / (C_DIM / 4);
    int c4 = i % (C_DIM / 4);
    int r0 = g_tokrow[2 * t + 0];
    int r1 = g_tokrow[2 * t + 1];
    const float4* y4 = (const float4*)g_y;
    float4 a = y4[(size_t)r0 * (C_DIM / 4) + c4];
    float4 b = y4[(size_t)r1 * (C_DIM / 4) + c4];
    float4 o;
    o.x = a.x + b.x; o.y = a.y + b.y; o.z = a.z + b.z; o.w = a.w + b.w;
    ((float4*)out)[i] = o;
}

// ---------------- launch ----------------
extern "C" void kernel_launch(void* const* d_in, const int* in_sizes, int n_in,
                              void* d_out, int out_size) {
    const float* x   = (const float*)d_in[0];   // [2,2048,1024]
    const float* rw  = (const float*)d_in[1];   // [8,1024]
    const float* w1  = (const float*)d_in[2];   // [8,4096,1024]
    const float* b1  = (const float*)d_in[3];   // [8,4096]
    const float* w2  = (const float*)d_in[4];   // [8,1024,4096]
    const float* b2  = (const float*)d_in[5];   // [8,1024]
    float* out = (float*)d_out;                 // [2,2048,1024]

    zero_kernel<<<1, 32>>>();
    router_kernel<<<(T_TOK * 32) / 256, 256>>>(x, rw);
    scan_kernel<<<1, 1>>>();
    scatter_kernel<<<(T_TOK + 255) / 256, 256>>>();

    dim3 g1(FF_DIM / 128, ROWS / 128, E_NUM);   // (32, 64, 8), early-exit on dead tiles
    gemm1_kernel<<<g1, 256>>>(x, w1, b1);

    dim3 g2(C_DIM / 128, ROWS / 128, E_NUM);    // (8, 64, 8)
    gemm2_kernel<<<g2, 256>>>(w2, b2);

    combine_kernel<<<(T_TOK * (C_DIM / 4)) / 256, 256>>>(out);
}

// round 4
// speedup vs baseline: 2.2769x; 2.2769x over previous
#include <cuda_runtime.h>
#include <cuda_bf16.h>
#include <math.h>
#include <stdint.h>

#define T_TOK   4096
#define C_DIM   1024
#define FF_DIM  4096
#define E_NUM   8
#define PROWS   9216            // 8192 rows + per-expert pad to 128
#define MTILES  (PROWS/128)     // 72

#define LDSE    40              // padded bf16 elems per 32-elem row (80B stride)
#define TILE_B  (128*LDSE*2)    // 10240 bytes per tile
#define STAGE_B (4*TILE_B)      // Ahi Alo Bhi Blo = 40960
#define NSTAGE  3
#define SMEM_TOTAL (NSTAGE*STAGE_B)   // 122880

// ---------------- scratch (static device globals; no allocation) ----------------
__device__ int   g_counts[E_NUM];
__device__ int   g_aoff[E_NUM];
__device__ int   g_cursor[E_NUM];
__device__ int   g_tile_e[MTILES];
__device__ int   g_top_idx[T_TOK * 2];
__device__ float g_top_w[T_TOK * 2];
__device__ int   g_rowtok[PROWS];
__device__ float g_rowgate[PROWS];
__device__ int   g_tokrow[T_TOK * 2];

__device__ __align__(128) __nv_bfloat16 g_a_hi[(size_t)PROWS * C_DIM];
__device__ __align__(128) __nv_bfloat16 g_a_lo[(size_t)PROWS * C_DIM];
__device__ __align__(128) __nv_bfloat16 g_w1_hi[(size_t)E_NUM * FF_DIM * C_DIM];
__device__ __align__(128) __nv_bfloat16 g_w1_lo[(size_t)E_NUM * FF_DIM * C_DIM];
__device__ __align__(128) __nv_bfloat16 g_w2_hi[(size_t)E_NUM * C_DIM * FF_DIM];
__device__ __align__(128) __nv_bfloat16 g_w2_lo[(size_t)E_NUM * C_DIM * FF_DIM];
__device__ __align__(128) __nv_bfloat16 g_h_hi[(size_t)PROWS * FF_DIM];
__device__ __align__(128) __nv_bfloat16 g_h_lo[(size_t)PROWS * FF_DIM];
__device__ __align__(128) float         g_y[(size_t)PROWS * C_DIM];

// ---------------- PTX helpers (baseline-PTX only; no 'a'-target features) ------
__device__ __forceinline__ uint32_t s2u(const void* p) {
    uint32_t a;
    asm("{ .reg .u64 t; cvta.to.shared.u64 t, %1; cvt.u32.u64 %0, t; }" : "=r"(a) : "l"(p));
    return a;
}
__device__ __forceinline__ void cpasync16(uint32_t dst, const void* src) {
    asm volatile("cp.async.cg.shared.global [%0], [%1], 16;" :: "r"(dst), "l"(src));
}
__device__ __forceinline__ void cp_commit() {
    asm volatile("cp.async.commit_group;" ::: "memory");
}
__device__ __forceinline__ void ldmx4(uint32_t* r, uint32_t addr) {
    asm volatile("ldmatrix.sync.aligned.m8n8.x4.shared.b16 {%0,%1,%2,%3}, [%4];"
                 : "=r"(r[0]), "=r"(r[1]), "=r"(r[2]), "=r"(r[3]) : "r"(addr));
}
__device__ __forceinline__ void mma16816(float* c, const uint32_t* a, const uint32_t* b) {
    asm volatile("mma.sync.aligned.m16n8k16.row.col.f32.bf16.bf16.f32 "
                 "{%0,%1,%2,%3}, {%4,%5,%6,%7}, {%8,%9}, {%0,%1,%2,%3};"
                 : "+f"(c[0]), "+f"(c[1]), "+f"(c[2]), "+f"(c[3])
                 : "r"(a[0]), "r"(a[1]), "r"(a[2]), "r"(a[3]), "r"(b[0]), "r"(b[1]));
}

// ---------------- routing ----------------
__global__ void init_kernel() {
    int i = blockIdx.x * blockDim.x + threadIdx.x;
    if (i < E_NUM) g_counts[i] = 0;
    if (i < PROWS) g_rowtok[i] = -1;
}

__global__ void router_kernel(const float* __restrict__ x, const float* __restrict__ rw) {
    int gtid = blockIdx.x * blockDim.x + threadIdx.x;
    int t = gtid >> 5, lane = threadIdx.x & 31;
    if (t >= T_TOK) return;
    const float4* xr4 = (const float4*)(x + (size_t)t * C_DIM);
    const float4* rw4 = (const float4*)rw;
    float acc[E_NUM];
#pragma unroll
    for (int e = 0; e < E_NUM; e++) acc[e] = 0.f;
    for (int c4 = lane; c4 < C_DIM / 4; c4 += 32) {
        float4 xv = xr4[c4];
#pragma unroll
        for (int e = 0; e < E_NUM; e++) {
            float4 wv = rw4[e * (C_DIM / 4) + c4];
            acc[e] += xv.x * wv.x + xv.y * wv.y + xv.z * wv.z + xv.w * wv.w;
        }
    }
#pragma unroll
    for (int e = 0; e < E_NUM; e++)
#pragma unroll
        for (int o = 16; o; o >>= 1) acc[e] += __shfl_xor_sync(0xFFFFFFFFu, acc[e], o);
    if (lane == 0) {
        float m = acc[0];
#pragma unroll
        for (int e = 1; e < E_NUM; e++) m = fmaxf(m, acc[e]);
        float p[E_NUM], Z = 0.f;
#pragma unroll
        for (int e = 0; e < E_NUM; e++) { p[e] = expf(acc[e] - m); Z += p[e]; }
#pragma unroll
        for (int e = 0; e < E_NUM; e++) p[e] /= Z;
        int i0 = 0;
#pragma unroll
        for (int e = 1; e < E_NUM; e++) if (p[e] > p[i0]) i0 = e;
        int i1 = (i0 == 0) ? 1 : 0;
#pragma unroll
        for (int e = 0; e < E_NUM; e++) if (e != i0 && p[e] > p[i1]) i1 = e;
        float s = p[i0] + p[i1] + 1e-9f;
        g_top_idx[2 * t + 0] = i0; g_top_w[2 * t + 0] = p[i0] / s;
        g_top_idx[2 * t + 1] = i1; g_top_w[2 * t + 1] = p[i1] / s;
        atomicAdd(&g_counts[i0], 1);
        atomicAdd(&g_counts[i1], 1);
    }
}

__global__ void scan_kernel() {
    if (threadIdx.x == 0) {
        int o = 0;
        for (int e = 0; e < E_NUM; e++) {
            g_aoff[e] = o; g_cursor[e] = o;
            int a = (g_counts[e] + 127) & ~127;
            for (int t = o / 128; t < (o + a) / 128; t++) g_tile_e[t] = e;
            o += a;
        }
        for (int t = o / 128; t < MTILES; t++) g_tile_e[t] = E_NUM - 1;
    }
}

__global__ void scatter_kernel() {
    int t = blockIdx.x * blockDim.x + threadIdx.x;
    if (t >= T_TOK) return;
#pragma unroll
    for (int k = 0; k < 2; k++) {
        int e = g_top_idx[2 * t + k];
        int row = atomicAdd(&g_cursor[e], 1);
        g_rowtok[row] = t;
        g_rowgate[row] = g_top_w[2 * t + k];
        g_tokrow[2 * t + k] = row;
    }
}

// ---------------- bf16 hi/lo conversions ----------------
__device__ __forceinline__ void split4(float4 v, uint2& hi, uint2& lo) {
    __nv_bfloat16 h0 = __float2bfloat16_rn(v.x), h1 = __float2bfloat16_rn(v.y);
    __nv_bfloat16 h2 = __float2bfloat16_rn(v.z), h3 = __float2bfloat16_rn(v.w);
    __nv_bfloat16 l0 = __float2bfloat16_rn(v.x - __bfloat162float(h0));
    __nv_bfloat16 l1 = __float2bfloat16_rn(v.y - __bfloat162float(h1));
    __nv_bfloat16 l2 = __float2bfloat16_rn(v.z - __bfloat162float(h2));
    __nv_bfloat16 l3 = __float2bfloat16_rn(v.w - __bfloat162float(h3));
    hi.x = (uint32_t)__bfloat16_as_ushort(h0) | ((uint32_t)__bfloat16_as_ushort(h1) << 16);
    hi.y = (uint32_t)__bfloat16_as_ushort(h2) | ((uint32_t)__bfloat16_as_ushort(h3) << 16);
    lo.x = (uint32_t)__bfloat16_as_ushort(l0) | ((uint32_t)__bfloat16_as_ushort(l1) << 16);
    lo.y = (uint32_t)__bfloat16_as_ushort(l2) | ((uint32_t)__bfloat16_as_ushort(l3) << 16);
}

__global__ void convert_w_kernel(const float* __restrict__ w, __nv_bfloat16* __restrict__ hi,
                                 __nv_bfloat16* __restrict__ lo, int n4) {
    int i = blockIdx.x * blockDim.x + threadIdx.x;
    if (i >= n4) return;
    float4 v = ((const float4*)w)[i];
    uint2 h, l;
    split4(v, h, l);
    ((uint2*)hi)[i] = h;
    ((uint2*)lo)[i] = l;
}

__global__ void gather_kernel(const float* __restrict__ x) {
    int idx = blockIdx.x * blockDim.x + threadIdx.x;   // over PROWS * 256
    int r = idx >> 8, c4 = idx & 255;
    int t = g_rowtok[r];
    float4 v = make_float4(0.f, 0.f, 0.f, 0.f);
    if (t >= 0) v = ((const float4*)x)[(size_t)t * 256 + c4];
    uint2 h, l;
    split4(v, h, l);
    ((uint2*)g_a_hi)[(size_t)r * 256 + c4] = h;
    ((uint2*)g_a_lo)[(size_t)r * 256 + c4] = l;
}

// ---------------- mma.sync GEMM (bf16x3 split precision) ----------------
// MODE 0: H = gelu(A@W1^T + b1), store bf16 hi/lo.  MODE 1: Y = (A@W2^T + b2)*gate, fp32.
template <int MODE, int KDIM>
__global__ void __launch_bounds__(256) gemm_mma(
    const __nv_bfloat16* __restrict__ Ah, const __nv_bfloat16* __restrict__ Al,
    const __nv_bfloat16* __restrict__ Bh, const __nv_bfloat16* __restrict__ Bl,
    const float* __restrict__ bias, int NDIM) {

    int e  = g_tile_e[blockIdx.y];
    int m0 = blockIdx.y * 128;
    if (m0 >= g_aoff[e] + g_counts[e]) return;
    int n0    = blockIdx.x * 128;
    int bbase = e * NDIM + n0;

    extern __shared__ char smem[];
    uint32_t sb  = s2u(smem);
    int tid  = threadIdx.x;
    int lane = tid & 31, wid = tid >> 5;
    int wm = wid >> 2, wn = wid & 3;   // 2x4 warp grid, warp tile 64x32

    const int NCH = KDIM / 32;

    auto load_stage = [&](int c, int st) {
        int k0 = c * 32;
        uint32_t stg = sb + st * STAGE_B;
#pragma unroll
        for (int i = 0; i < 8; i++) {
            int ci = i * 256 + tid;
            int tile = ci >> 9, rc = ci & 511, row = rc >> 2, c16 = rc & 3;
            uint32_t dst = stg + tile * TILE_B + row * 80 + c16 * 16;
            const __nv_bfloat16* src;
            if (tile == 0)      src = Ah + (size_t)(m0 + row) * KDIM;
            else if (tile == 1) src = Al + (size_t)(m0 + row) * KDIM;
            else if (tile == 2) src = Bh + (size_t)(bbase + row) * KDIM;
            else                src = Bl + (size_t)(bbase + row) * KDIM;
            cpasync16(dst, src + k0 + c16 * 8);
        }
        cp_commit();
    };

    // ldmatrix element offsets (bf16 elements within a 128xLDSE tile)
    int aoff = (wm * 64 + (lane & 15)) * LDSE + (lane >> 4) * 8;
    int boff = (wn * 32 + ((lane >> 4) << 3) + (lane & 7)) * LDSE + ((lane >> 3) & 1) * 8;

    float acc[4][4][4];
#pragma unroll
    for (int a = 0; a < 4; a++)
#pragma unroll
        for (int b = 0; b < 4; b++)
#pragma unroll
            for (int q = 0; q < 4; q++) acc[a][b][q] = 0.f;

    load_stage(0, 0);
    load_stage(1, 1);

    for (int c = 0; c < NCH; c++) {
        if (c + 1 < NCH) asm volatile("cp.async.wait_group 1;" ::: "memory");
        else             asm volatile("cp.async.wait_group 0;" ::: "memory");
        __syncthreads();
        if (c + 2 < NCH) load_stage(c + 2, (c + 2) % NSTAGE);

        uint32_t stg = sb + (c % NSTAGE) * STAGE_B;
        uint32_t aH = stg + aoff * 2;
        uint32_t aL = stg + TILE_B + aoff * 2;
        uint32_t bH = stg + 2 * TILE_B + boff * 2;
        uint32_t bL = stg + 3 * TILE_B + boff * 2;

#pragma unroll
        for (int kk = 0; kk < 2; kk++) {
            uint32_t k2 = kk * 32;   // 16 bf16 = 32 bytes
            uint32_t ah[4][4], al[4][4], bh[2][4], bl[2][4];
#pragma unroll
            for (int f = 0; f < 4; f++) ldmx4(ah[f], aH + f * (16 * LDSE * 2) + k2);
#pragma unroll
            for (int g = 0; g < 2; g++) ldmx4(bh[g], bH + g * (16 * LDSE * 2) + k2);
#pragma unroll
            for (int mi = 0; mi < 4; mi++)
#pragma unroll
                for (int g = 0; g < 2; g++) {
                    mma16816(acc[mi][g * 2 + 0], ah[mi], &bh[g][0]);
                    mma16816(acc[mi][g * 2 + 1], ah[mi], &bh[g][2]);
                }
#pragma unroll
            for (int g = 0; g < 2; g++) ldmx4(bl[g], bL + g * (16 * LDSE * 2) + k2);
#pragma unroll
            for (int mi = 0; mi < 4; mi++)
#pragma unroll
                for (int g = 0; g < 2; g++) {
                    mma16816(acc[mi][g * 2 + 0], ah[mi], &bl[g][0]);
                    mma16816(acc[mi][g * 2 + 1], ah[mi], &bl[g][2]);
                }
#pragma unroll
            for (int f = 0; f < 4; f++) ldmx4(al[f], aL + f * (16 * LDSE * 2) + k2);
#pragma unroll
            for (int mi = 0; mi < 4; mi++)
#pragma unroll
                for (int g = 0; g < 2; g++) {
                    mma16816(acc[mi][g * 2 + 0], al[mi], &bh[g][0]);
                    mma16816(acc[mi][g * 2 + 1], al[mi], &bh[g][2]);
                }
        }
    }

    // ---------------- epilogue ----------------
    int rbase = m0 + wm * 64 + (lane >> 2);
#pragma unroll
    for (int mi = 0; mi < 4; mi++) {
#pragma unroll
        for (int rr = 0; rr < 2; rr++) {          // row lane/4 and +8
            int r = rbase + mi * 16 + rr * 8;
#pragma unroll
            for (int ni = 0; ni < 4; ni++) {
                int coln = n0 + wn * 32 + ni * 8 + (lane & 3) * 2;   // local N col (even)
                float v0 = acc[mi][ni][rr * 2 + 0] + bias[e * NDIM + coln];
                float v1 = acc[mi][ni][rr * 2 + 1] + bias[e * NDIM + coln + 1];
                if (MODE == 0) {
                    v0 = 0.5f * v0 * (1.f + erff(v0 * 0.70710678118654752f));
                    v1 = 0.5f * v1 * (1.f + erff(v1 * 0.70710678118654752f));
                    __nv_bfloat16 h0 = __float2bfloat16_rn(v0), h1 = __float2bfloat16_rn(v1);
                    __nv_bfloat16 l0 = __float2bfloat16_rn(v0 - __bfloat162float(h0));
                    __nv_bfloat16 l1 = __float2bfloat16_rn(v1 - __bfloat162float(h1));
                    uint32_t hp = (uint32_t)__bfloat16_as_ushort(h0) | ((uint32_t)__bfloat16_as_ushort(h1) << 16);
                    uint32_t lp = (uint32_t)__bfloat16_as_ushort(l0) | ((uint32_t)__bfloat16_as_ushort(l1) << 16);
                    *(uint32_t*)&g_h_hi[(size_t)r * FF_DIM + coln] = hp;
                    *(uint32_t*)&g_h_lo[(size_t)r * FF_DIM + coln] = lp;
                } else {
                    float gate = g_rowgate[r];
                    float2 o = make_float2(v0 * gate, v1 * gate);
                    *(float2*)&g_y[(size_t)r * C_DIM + coln] = o;
                }
            }
        }
    }
}

// ---------------- combine ----------------
__global__ void combine_kernel(float* __restrict__ out) {
    int i = blockIdx.x * blockDim.x + threadIdx.x;   // T_TOK * 256
    if (i >= T_TOK * (C_DIM / 4)) return;
    int t = i >> 8, c4 = i & 255;
    int r0 = g_tokrow[2 * t + 0];
    int r1 = g_tokrow[2 * t + 1];
    const float4* y4 = (const float4*)g_y;
    float4 a = y4[(size_t)r0 * 256 + c4];
    float4 b = y4[(size_t)r1 * 256 + c4];
    ((float4*)out)[i] = make_float4(a.x + b.x, a.y + b.y, a.z + b.z, a.w + b.w);
}

// ---------------- host ----------------
extern "C" void kernel_launch(void* const* d_in, const int* in_sizes, int n_in,
                              void* d_out, int out_size) {
    const float* x  = (const float*)d_in[0];
    const float* rw = (const float*)d_in[1];
    const float* w1 = (const float*)d_in[2];
    const float* b1 = (const float*)d_in[3];
    const float* w2 = (const float*)d_in[4];
    const float* b2 = (const float*)d_in[5];
    float* out = (float*)d_out;

    void *pAh, *pAl, *pW1h, *pW1l, *pW2h, *pW2l, *pHh, *pHl;
    cudaGetSymbolAddress(&pAh, g_a_hi);   cudaGetSymbolAddress(&pAl, g_a_lo);
    cudaGetSymbolAddress(&pW1h, g_w1_hi); cudaGetSymbolAddress(&pW1l, g_w1_lo);
    cudaGetSymbolAddress(&pW2h, g_w2_hi); cudaGetSymbolAddress(&pW2l, g_w2_lo);
    cudaGetSymbolAddress(&pHh, g_h_hi);   cudaGetSymbolAddress(&pHl, g_h_lo);

    cudaFuncSetAttribute(gemm_mma<0, C_DIM>,  cudaFuncAttributeMaxDynamicSharedMemorySize, SMEM_TOTAL);
    cudaFuncSetAttribute(gemm_mma<1, FF_DIM>, cudaFuncAttributeMaxDynamicSharedMemorySize, SMEM_TOTAL);

    init_kernel<<<PROWS / 256, 256>>>();
    router_kernel<<<(T_TOK * 32) / 256, 256>>>(x, rw);
    scan_kernel<<<1, 1>>>();
    scatter_kernel<<<T_TOK / 256, 256>>>();
    gather_kernel<<<PROWS, 256>>>(x);

    int n4w = E_NUM * FF_DIM * C_DIM / 4;
    convert_w_kernel<<<n4w / 256, 256>>>(w1, (__nv_bfloat16*)pW1h, (__nv_bfloat16*)pW1l, n4w);
    convert_w_kernel<<<n4w / 256, 256>>>(w2, (__nv_bfloat16*)pW2h, (__nv_bfloat16*)pW2l, n4w);

    dim3 g1(FF_DIM / 128, MTILES);   // (32, 72)
    gemm_mma<0, C_DIM><<<g1, 256, SMEM_TOTAL>>>(
        (const __nv_bfloat16*)pAh, (const __nv_bfloat16*)pAl,
        (const __nv_bfloat16*)pW1h, (const __nv_bfloat16*)pW1l, b1, FF_DIM);

    dim3 g2(C_DIM / 128, MTILES);    // (8, 72)
    gemm_mma<1, FF_DIM><<<g2, 256, SMEM_TOTAL>>>(
        (const __nv_bfloat16*)pHh, (const __nv_bfloat16*)pHl,
        (const __nv_bfloat16*)pW2h, (const __nv_bfloat16*)pW2l, b2, C_DIM);

    combine_kernel<<<(T_TOK * (C_DIM / 4)) / 256, 256>>>(out);
}

// round 5
// speedup vs baseline: 3.5798x; 1.5722x over previous
#include <cuda_runtime.h>
#include <cuda_fp16.h>
#include <math.h>
#include <stdint.h>

#define T_TOK   4096
#define C_DIM   1024
#define FF_DIM  4096
#define E_NUM   8
#define PROWS   9216            // 8192 rows + per-expert pad to 128
#define MTILES  (PROWS/128)     // 72

#define LDSE    40              // padded fp16 elems per 32-elem row (80B stride)
#define TILE_B  (128*LDSE*2)    // 10240 bytes per tile
#define STAGE_B (3*TILE_B)      // Ahi Alo Bhi = 30720
#define NSTAGE  3
#define SMEM_TOTAL (NSTAGE*STAGE_B)   // 92160 -> 2 CTAs/SM

// ---------------- scratch (static device globals; no allocation) ----------------
__device__ int   g_counts[E_NUM];
__device__ int   g_aoff[E_NUM];
__device__ int   g_cursor[E_NUM];
__device__ int   g_tile_e[MTILES];
__device__ int   g_top_idx[T_TOK * 2];
__device__ float g_top_w[T_TOK * 2];
__device__ int   g_rowtok[PROWS];
__device__ float g_rowgate[PROWS];
__device__ int   g_tokrow[T_TOK * 2];

__device__ __align__(128) __half g_a_hi[(size_t)PROWS * C_DIM];
__device__ __align__(128) __half g_a_lo[(size_t)PROWS * C_DIM];
__device__ __align__(128) __half g_w1_hi[(size_t)E_NUM * FF_DIM * C_DIM];
__device__ __align__(128) __half g_w2_hi[(size_t)E_NUM * C_DIM * FF_DIM];
__device__ __align__(128) __half g_h_hi[(size_t)PROWS * FF_DIM];
__device__ __align__(128) __half g_h_lo[(size_t)PROWS * FF_DIM];
__device__ __align__(128) float  g_y[(size_t)PROWS * C_DIM];

// ---------------- PTX helpers (baseline-PTX only) ----------------
__device__ __forceinline__ uint32_t s2u(const void* p) {
    uint32_t a;
    asm("{ .reg .u64 t; cvta.to.shared.u64 t, %1; cvt.u32.u64 %0, t; }" : "=r"(a) : "l"(p));
    return a;
}
__device__ __forceinline__ void cpasync16(uint32_t dst, const void* src) {
    asm volatile("cp.async.cg.shared.global [%0], [%1], 16;" :: "r"(dst), "l"(src));
}
__device__ __forceinline__ void cp_commit() {
    asm volatile("cp.async.commit_group;" ::: "memory");
}
__device__ __forceinline__ void ldmx4(uint32_t* r, uint32_t addr) {
    asm volatile("ldmatrix.sync.aligned.m8n8.x4.shared.b16 {%0,%1,%2,%3}, [%4];"
                 : "=r"(r[0]), "=r"(r[1]), "=r"(r[2]), "=r"(r[3]) : "r"(addr));
}
__device__ __forceinline__ void mma16816(float* c, const uint32_t* a, const uint32_t* b) {
    asm volatile("mma.sync.aligned.m16n8k16.row.col.f32.f16.f16.f32 "
                 "{%0,%1,%2,%3}, {%4,%5,%6,%7}, {%8,%9}, {%0,%1,%2,%3};"
                 : "+f"(c[0]), "+f"(c[1]), "+f"(c[2]), "+f"(c[3])
                 : "r"(a[0]), "r"(a[1]), "r"(a[2]), "r"(a[3]), "r"(b[0]), "r"(b[1]));
}

// ---------------- routing ----------------
__global__ void init_kernel() {
    int i = blockIdx.x * blockDim.x + threadIdx.x;
    if (i < E_NUM) g_counts[i] = 0;
    if (i < PROWS) g_rowtok[i] = -1;
}

__global__ void router_kernel(const float* __restrict__ x, const float* __restrict__ rw) {
    int gtid = blockIdx.x * blockDim.x + threadIdx.x;
    int t = gtid >> 5, lane = threadIdx.x & 31;
    if (t >= T_TOK) return;
    const float4* xr4 = (const float4*)(x + (size_t)t * C_DIM);
    const float4* rw4 = (const float4*)rw;
    float acc[E_NUM];
#pragma unroll
    for (int e = 0; e < E_NUM; e++) acc[e] = 0.f;
    for (int c4 = lane; c4 < C_DIM / 4; c4 += 32) {
        float4 xv = xr4[c4];
#pragma unroll
        for (int e = 0; e < E_NUM; e++) {
            float4 wv = rw4[e * (C_DIM / 4) + c4];
            acc[e] += xv.x * wv.x + xv.y * wv.y + xv.z * wv.z + xv.w * wv.w;
        }
    }
#pragma unroll
    for (int e = 0; e < E_NUM; e++)
#pragma unroll
        for (int o = 16; o; o >>= 1) acc[e] += __shfl_xor_sync(0xFFFFFFFFu, acc[e], o);
    if (lane == 0) {
        float m = acc[0];
#pragma unroll
        for (int e = 1; e < E_NUM; e++) m = fmaxf(m, acc[e]);
        float p[E_NUM], Z = 0.f;
#pragma unroll
        for (int e = 0; e < E_NUM; e++) { p[e] = expf(acc[e] - m); Z += p[e]; }
#pragma unroll
        for (int e = 0; e < E_NUM; e++) p[e] /= Z;
        int i0 = 0;
#pragma unroll
        for (int e = 1; e < E_NUM; e++) if (p[e] > p[i0]) i0 = e;
        int i1 = (i0 == 0) ? 1 : 0;
#pragma unroll
        for (int e = 0; e < E_NUM; e++) if (e != i0 && p[e] > p[i1]) i1 = e;
        float s = p[i0] + p[i1] + 1e-9f;
        g_top_idx[2 * t + 0] = i0; g_top_w[2 * t + 0] = p[i0] / s;
        g_top_idx[2 * t + 1] = i1; g_top_w[2 * t + 1] = p[i1] / s;
        atomicAdd(&g_counts[i0], 1);
        atomicAdd(&g_counts[i1], 1);
    }
}

__global__ void scan_kernel() {
    if (threadIdx.x == 0) {
        int o = 0;
        for (int e = 0; e < E_NUM; e++) {
            g_aoff[e] = o; g_cursor[e] = o;
            int a = (g_counts[e] + 127) & ~127;
            for (int t = o / 128; t < (o + a) / 128; t++) g_tile_e[t] = e;
            o += a;
        }
        for (int t = o / 128; t < MTILES; t++) g_tile_e[t] = E_NUM - 1;
    }
}

__global__ void scatter_kernel() {
    int t = blockIdx.x * blockDim.x + threadIdx.x;
    if (t >= T_TOK) return;
#pragma unroll
    for (int k = 0; k < 2; k++) {
        int e = g_top_idx[2 * t + k];
        int row = atomicAdd(&g_cursor[e], 1);
        g_rowtok[row] = t;
        g_rowgate[row] = g_top_w[2 * t + k];
        g_tokrow[2 * t + k] = row;
    }
}

// ---------------- fp16 conversions ----------------
__device__ __forceinline__ void split4h(float4 v, uint2& hi, uint2& lo) {
    __half h0 = __float2half_rn(v.x), h1 = __float2half_rn(v.y);
    __half h2 = __float2half_rn(v.z), h3 = __float2half_rn(v.w);
    __half l0 = __float2half_rn(v.x - __half2float(h0));
    __half l1 = __float2half_rn(v.y - __half2float(h1));
    __half l2 = __float2half_rn(v.z - __half2float(h2));
    __half l3 = __float2half_rn(v.w - __half2float(h3));
    hi.x = (uint32_t)__half_as_ushort(h0) | ((uint32_t)__half_as_ushort(h1) << 16);
    hi.y = (uint32_t)__half_as_ushort(h2) | ((uint32_t)__half_as_ushort(h3) << 16);
    lo.x = (uint32_t)__half_as_ushort(l0) | ((uint32_t)__half_as_ushort(l1) << 16);
    lo.y = (uint32_t)__half_as_ushort(l2) | ((uint32_t)__half_as_ushort(l3) << 16);
}

// weights: hi only (B-side truncation; error ~2^-11 handled by margin)
__global__ void convert_w_kernel(const float* __restrict__ w, __half* __restrict__ hi, int n4) {
    int i = blockIdx.x * blockDim.x + threadIdx.x;
    if (i >= n4) return;
    float4 v = ((const float4*)w)[i];
    __half h0 = __float2half_rn(v.x), h1 = __float2half_rn(v.y);
    __half h2 = __float2half_rn(v.z), h3 = __float2half_rn(v.w);
    uint2 h;
    h.x = (uint32_t)__half_as_ushort(h0) | ((uint32_t)__half_as_ushort(h1) << 16);
    h.y = (uint32_t)__half_as_ushort(h2) | ((uint32_t)__half_as_ushort(h3) << 16);
    ((uint2*)hi)[i] = h;
}

__global__ void gather_kernel(const float* __restrict__ x) {
    int idx = blockIdx.x * blockDim.x + threadIdx.x;   // over PROWS * 256
    int r = idx >> 8, c4 = idx & 255;
    int t = g_rowtok[r];
    float4 v = make_float4(0.f, 0.f, 0.f, 0.f);
    if (t >= 0) v = ((const float4*)x)[(size_t)t * 256 + c4];
    uint2 h, l;
    split4h(v, h, l);
    ((uint2*)g_a_hi)[(size_t)r * 256 + c4] = h;
    ((uint2*)g_a_lo)[(size_t)r * 256 + c4] = l;
}

// ---------------- mma.sync GEMM (fp16x2: (Ahi+Alo)@Bhi) ----------------
// MODE 0: H = gelu(A@W1^T + b1) -> fp16 hi/lo.  MODE 1: Y = (A@W2^T + b2)*gate -> fp32.
template <int MODE, int KDIM>
__global__ void __launch_bounds__(256, 2) gemm_mma(
    const __half* __restrict__ Ah, const __half* __restrict__ Al,
    const __half* __restrict__ Bh,
    const float* __restrict__ bias, int NDIM) {

    int e  = g_tile_e[blockIdx.y];
    int m0 = blockIdx.y * 128;
    if (m0 >= g_aoff[e] + g_counts[e]) return;
    int n0    = blockIdx.x * 128;
    int bbase = e * NDIM + n0;

    extern __shared__ char smem[];
    uint32_t sb  = s2u(smem);
    int tid  = threadIdx.x;
    int lane = tid & 31, wid = tid >> 5;
    int wm = wid >> 2, wn = wid & 3;   // 2x4 warp grid, warp tile 64x32

    const int NCH = KDIM / 32;

    auto load_stage = [&](int c, int st) {
        int k0 = c * 32;
        uint32_t stg = sb + st * STAGE_B;
#pragma unroll
        for (int i = 0; i < 6; i++) {               // 3 tiles * 512 chunks
            int ci = i * 256 + tid;
            int tile = ci >> 9, rc = ci & 511, row = rc >> 2, c16 = rc & 3;
            uint32_t dst = stg + tile * TILE_B + row * 80 + c16 * 16;
            const __half* src;
            if (tile == 0)      src = Ah + (size_t)(m0 + row) * KDIM;
            else if (tile == 1) src = Al + (size_t)(m0 + row) * KDIM;
            else                src = Bh + (size_t)(bbase + row) * KDIM;
            cpasync16(dst, src + k0 + c16 * 8);
        }
        cp_commit();
    };

    int aoff = (wm * 64 + (lane & 15)) * LDSE + (lane >> 4) * 8;
    int boff = (wn * 32 + ((lane >> 4) << 3) + (lane & 7)) * LDSE + ((lane >> 3) & 1) * 8;

    float acc[4][4][4];
#pragma unroll
    for (int a = 0; a < 4; a++)
#pragma unroll
        for (int b = 0; b < 4; b++)
#pragma unroll
            for (int q = 0; q < 4; q++) acc[a][b][q] = 0.f;

    load_stage(0, 0);
    load_stage(1, 1);

    for (int c = 0; c < NCH; c++) {
        if (c + 1 < NCH) asm volatile("cp.async.wait_group 1;" ::: "memory");
        else             asm volatile("cp.async.wait_group 0;" ::: "memory");
        __syncthreads();
        if (c + 2 < NCH) load_stage(c + 2, (c + 2) % NSTAGE);

        uint32_t stg = sb + (c % NSTAGE) * STAGE_B;
        uint32_t aH = stg + aoff * 2;
        uint32_t aL = stg + TILE_B + aoff * 2;
        uint32_t bH = stg + 2 * TILE_B + boff * 2;

#pragma unroll
        for (int kk = 0; kk < 2; kk++) {
            uint32_t k2 = kk * 32;   // 16 fp16 = 32 bytes
            uint32_t bh[2][4];
#pragma unroll
            for (int g = 0; g < 2; g++) ldmx4(bh[g], bH + g * (16 * LDSE * 2) + k2);
            {   // pass 1: Ahi @ Bhi
                uint32_t ah[4][4];
#pragma unroll
                for (int f = 0; f < 4; f++) ldmx4(ah[f], aH + f * (16 * LDSE * 2) + k2);
#pragma unroll
                for (int mi = 0; mi < 4; mi++)
#pragma unroll
                    for (int g = 0; g < 2; g++) {
                        mma16816(acc[mi][g * 2 + 0], ah[mi], &bh[g][0]);
                        mma16816(acc[mi][g * 2 + 1], ah[mi], &bh[g][2]);
                    }
            }
            {   // pass 2: Alo @ Bhi
                uint32_t al[4][4];
#pragma unroll
                for (int f = 0; f < 4; f++) ldmx4(al[f], aL + f * (16 * LDSE * 2) + k2);
#pragma unroll
                for (int mi = 0; mi < 4; mi++)
#pragma unroll
                    for (int g = 0; g < 2; g++) {
                        mma16816(acc[mi][g * 2 + 0], al[mi], &bh[g][0]);
                        mma16816(acc[mi][g * 2 + 1], al[mi], &bh[g][2]);
                    }
            }
        }
    }

    // ---------------- epilogue ----------------
    int rbase = m0 + wm * 64 + (lane >> 2);
#pragma unroll
    for (int mi = 0; mi < 4; mi++) {
#pragma unroll
        for (int rr = 0; rr < 2; rr++) {
            int r = rbase + mi * 16 + rr * 8;
#pragma unroll
            for (int ni = 0; ni < 4; ni++) {
                int coln = n0 + wn * 32 + ni * 8 + (lane & 3) * 2;
                float v0 = acc[mi][ni][rr * 2 + 0] + bias[e * NDIM + coln];
                float v1 = acc[mi][ni][rr * 2 + 1] + bias[e * NDIM + coln + 1];
                if (MODE == 0) {
                    v0 = 0.5f * v0 * (1.f + erff(v0 * 0.70710678118654752f));
                    v1 = 0.5f * v1 * (1.f + erff(v1 * 0.70710678118654752f));
                    __half h0 = __float2half_rn(v0), h1 = __float2half_rn(v1);
                    __half l0 = __float2half_rn(v0 - __half2float(h0));
                    __half l1 = __float2half_rn(v1 - __half2float(h1));
                    uint32_t hp = (uint32_t)__half_as_ushort(h0) | ((uint32_t)__half_as_ushort(h1) << 16);
                    uint32_t lp = (uint32_t)__half_as_ushort(l0) | ((uint32_t)__half_as_ushort(l1) << 16);
                    *(uint32_t*)&g_h_hi[(size_t)r * FF_DIM + coln] = hp;
                    *(uint32_t*)&g_h_lo[(size_t)r * FF_DIM + coln] = lp;
                } else {
                    float gate = g_rowgate[r];
                    float2 o = make_float2(v0 * gate, v1 * gate);
                    *(float2*)&g_y[(size_t)r * C_DIM + coln] = o;
                }
            }
        }
    }
}

// ---------------- combine ----------------
__global__ void combine_kernel(float* __restrict__ out) {
    int i = blockIdx.x * blockDim.x + threadIdx.x;   // T_TOK * 256
    if (i >= T_TOK * (C_DIM / 4)) return;
    int t = i >> 8, c4 = i & 255;
    int r0 = g_tokrow[2 * t + 0];
    int r1 = g_tokrow[2 * t + 1];
    const float4* y4 = (const float4*)g_y;
    float4 a = y4[(size_t)r0 * 256 + c4];
    float4 b = y4[(size_t)r1 * 256 + c4];
    ((float4*)out)[i] = make_float4(a.x + b.x, a.y + b.y, a.z + b.z, a.w + b.w);
}

// ---------------- host ----------------
extern "C" void kernel_launch(void* const* d_in, const int* in_sizes, int n_in,
                              void* d_out, int out_size) {
    const float* x  = (const float*)d_in[0];
    const float* rw = (const float*)d_in[1];
    const float* w1 = (const float*)d_in[2];
    const float* b1 = (const float*)d_in[3];
    const float* w2 = (const float*)d_in[4];
    const float* b2 = (const float*)d_in[5];
    float* out = (float*)d_out;

    void *pAh, *pAl, *pW1h, *pW2h, *pHh, *pHl;
    cudaGetSymbolAddress(&pAh, g_a_hi);   cudaGetSymbolAddress(&pAl, g_a_lo);
    cudaGetSymbolAddress(&pW1h, g_w1_hi); cudaGetSymbolAddress(&pW2h, g_w2_hi);
    cudaGetSymbolAddress(&pHh, g_h_hi);   cudaGetSymbolAddress(&pHl, g_h_lo);

    cudaFuncSetAttribute(gemm_mma<0, C_DIM>,  cudaFuncAttributeMaxDynamicSharedMemorySize, SMEM_TOTAL);
    cudaFuncSetAttribute(gemm_mma<1, FF_DIM>, cudaFuncAttributeMaxDynamicSharedMemorySize, SMEM_TOTAL);

    init_kernel<<<PROWS / 256, 256>>>();
    router_kernel<<<(T_TOK * 32) / 256, 256>>>(x, rw);
    scan_kernel<<<1, 1>>>();
    scatter_kernel<<<T_TOK / 256, 256>>>();
    gather_kernel<<<PROWS, 256>>>(x);

    int n4w = E_NUM * FF_DIM * C_DIM / 4;
    convert_w_kernel<<<n4w / 256, 256>>>(w1, (__half*)pW1h, n4w);
    convert_w_kernel<<<n4w / 256, 256>>>(w2, (__half*)pW2h, n4w);

    dim3 g1(FF_DIM / 128, MTILES);   // (32, 72)
    gemm_mma<0, C_DIM><<<g1, 256, SMEM_TOTAL>>>(
        (const __half*)pAh, (const __half*)pAl, (const __half*)pW1h, b1, FF_DIM);

    dim3 g2(C_DIM / 128, MTILES);    // (8, 72)
    gemm_mma<1, FF_DIM><<<g2, 256, SMEM_TOTAL>>>(
        (const __half*)pHh, (const __half*)pHl, (const __half*)pW2h, b2, C_DIM);

    combine_kernel<<<(T_TOK * (C_DIM / 4)) / 256, 256>>>(out);
}

// round 6
// speedup vs baseline: 5.7438x; 1.6045x over previous
#include <cuda_runtime.h>
#include <cuda_fp16.h>
#include <math.h>
#include <stdint.h>

#define T_TOK   4096
#define C_DIM   1024
#define FF_DIM  4096
#define E_NUM   8
#define PROWS   9216            // 8192 rows + per-expert pad to 128
#define MTILES  (PROWS/128)     // 72

#define LDSE    40              // padded fp16 elems per 32-elem row (80B stride)
#define TILE_B  (128*LDSE*2)    // 10240 bytes per tile
#define STAGE_B (2*TILE_B)      // A + B = 20480
#define NSTAGE  4
#define SMEM_TOTAL (NSTAGE*STAGE_B)   // 81920 -> 2 CTAs/SM

// ---------------- scratch (static device globals; no allocation) ----------------
__device__ int   g_counts[E_NUM];
__device__ int   g_aoff[E_NUM];
__device__ int   g_cursor[E_NUM];
__device__ int   g_tile_e[MTILES];
__device__ int   g_top_idx[T_TOK * 2];
__device__ float g_top_w[T_TOK * 2];
__device__ int   g_rowtok[PROWS];
__device__ float g_rowgate[PROWS];
__device__ int   g_tokrow[T_TOK * 2];

__device__ __align__(128) __half g_a[(size_t)PROWS * C_DIM];
__device__ __align__(128) __half g_w1[(size_t)E_NUM * FF_DIM * C_DIM];
__device__ __align__(128) __half g_w2[(size_t)E_NUM * C_DIM * FF_DIM];
__device__ __align__(128) __half g_h[(size_t)PROWS * FF_DIM];
__device__ __align__(128) float  g_y[(size_t)PROWS * C_DIM];

// ---------------- PTX helpers (baseline-PTX only) ----------------
__device__ __forceinline__ uint32_t s2u(const void* p) {
    uint32_t a;
    asm("{ .reg .u64 t; cvta.to.shared.u64 t, %1; cvt.u32.u64 %0, t; }" : "=r"(a) : "l"(p));
    return a;
}
__device__ __forceinline__ void cpasync16(uint32_t dst, const void* src) {
    asm volatile("cp.async.cg.shared.global [%0], [%1], 16;" :: "r"(dst), "l"(src));
}
__device__ __forceinline__ void cp_commit() {
    asm volatile("cp.async.commit_group;" ::: "memory");
}
__device__ __forceinline__ void ldmx4(uint32_t* r, uint32_t addr) {
    asm volatile("ldmatrix.sync.aligned.m8n8.x4.shared.b16 {%0,%1,%2,%3}, [%4];"
                 : "=r"(r[0]), "=r"(r[1]), "=r"(r[2]), "=r"(r[3]) : "r"(addr));
}
__device__ __forceinline__ void mma16816(float* c, const uint32_t* a, const uint32_t* b) {
    asm volatile("mma.sync.aligned.m16n8k16.row.col.f32.f16.f16.f32 "
                 "{%0,%1,%2,%3}, {%4,%5,%6,%7}, {%8,%9}, {%0,%1,%2,%3};"
                 : "+f"(c[0]), "+f"(c[1]), "+f"(c[2]), "+f"(c[3])
                 : "r"(a[0]), "r"(a[1]), "r"(a[2]), "r"(a[3]), "r"(b[0]), "r"(b[1]));
}

// ---------------- routing ----------------
__global__ void init_kernel() {
    int i = blockIdx.x * blockDim.x + threadIdx.x;
    if (i < E_NUM) g_counts[i] = 0;
    if (i < PROWS) g_rowtok[i] = -1;
}

__global__ void router_kernel(const float* __restrict__ x, const float* __restrict__ rw) {
    int gtid = blockIdx.x * blockDim.x + threadIdx.x;
    int t = gtid >> 5, lane = threadIdx.x & 31;
    if (t >= T_TOK) return;
    const float4* xr4 = (const float4*)(x + (size_t)t * C_DIM);
    const float4* rw4 = (const float4*)rw;
    float acc[E_NUM];
#pragma unroll
    for (int e = 0; e < E_NUM; e++) acc[e] = 0.f;
    for (int c4 = lane; c4 < C_DIM / 4; c4 += 32) {
        float4 xv = xr4[c4];
#pragma unroll
        for (int e = 0; e < E_NUM; e++) {
            float4 wv = rw4[e * (C_DIM / 4) + c4];
            acc[e] += xv.x * wv.x + xv.y * wv.y + xv.z * wv.z + xv.w * wv.w;
        }
    }
#pragma unroll
    for (int e = 0; e < E_NUM; e++)
#pragma unroll
        for (int o = 16; o; o >>= 1) acc[e] += __shfl_xor_sync(0xFFFFFFFFu, acc[e], o);
    if (lane == 0) {
        float m = acc[0];
#pragma unroll
        for (int e = 1; e < E_NUM; e++) m = fmaxf(m, acc[e]);
        float p[E_NUM], Z = 0.f;
#pragma unroll
        for (int e = 0; e < E_NUM; e++) { p[e] = expf(acc[e] - m); Z += p[e]; }
#pragma unroll
        for (int e = 0; e < E_NUM; e++) p[e] /= Z;
        int i0 = 0;
#pragma unroll
        for (int e = 1; e < E_NUM; e++) if (p[e] > p[i0]) i0 = e;
        int i1 = (i0 == 0) ? 1 : 0;
#pragma unroll
        for (int e = 0; e < E_NUM; e++) if (e != i0 && p[e] > p[i1]) i1 = e;
        float s = p[i0] + p[i1] + 1e-9f;
        g_top_idx[2 * t + 0] = i0; g_top_w[2 * t + 0] = p[i0] / s;
        g_top_idx[2 * t + 1] = i1; g_top_w[2 * t + 1] = p[i1] / s;
        atomicAdd(&g_counts[i0], 1);
        atomicAdd(&g_counts[i1], 1);
    }
}

__global__ void scan_kernel() {
    if (threadIdx.x == 0) {
        int o = 0;
        for (int e = 0; e < E_NUM; e++) {
            g_aoff[e] = o; g_cursor[e] = o;
            int a = (g_counts[e] + 127) & ~127;
            for (int t = o / 128; t < (o + a) / 128; t++) g_tile_e[t] = e;
            o += a;
        }
        for (int t = o / 128; t < MTILES; t++) g_tile_e[t] = E_NUM - 1;
    }
}

__global__ void scatter_kernel() {
    int t = blockIdx.x * blockDim.x + threadIdx.x;
    if (t >= T_TOK) return;
#pragma unroll
    for (int k = 0; k < 2; k++) {
        int e = g_top_idx[2 * t + k];
        int row = atomicAdd(&g_cursor[e], 1);
        g_rowtok[row] = t;
        g_rowgate[row] = g_top_w[2 * t + k];
        g_tokrow[2 * t + k] = row;
    }
}

// ---------------- fp16 conversions ----------------
__global__ void convert_w_kernel(const float* __restrict__ w, __half* __restrict__ hi, int n4) {
    int i = blockIdx.x * blockDim.x + threadIdx.x;
    if (i >= n4) return;
    float4 v = ((const float4*)w)[i];
    __half h0 = __float2half_rn(v.x), h1 = __float2half_rn(v.y);
    __half h2 = __float2half_rn(v.z), h3 = __float2half_rn(v.w);
    uint2 h;
    h.x = (uint32_t)__half_as_ushort(h0) | ((uint32_t)__half_as_ushort(h1) << 16);
    h.y = (uint32_t)__half_as_ushort(h2) | ((uint32_t)__half_as_ushort(h3) << 16);
    ((uint2*)hi)[i] = h;
}

__global__ void gather_kernel(const float* __restrict__ x) {
    int idx = blockIdx.x * blockDim.x + threadIdx.x;   // over PROWS * 256
    int r = idx >> 8, c4 = idx & 255;
    int t = g_rowtok[r];
    float4 v = make_float4(0.f, 0.f, 0.f, 0.f);
    if (t >= 0) v = ((const float4*)x)[(size_t)t * 256 + c4];
    __half h0 = __float2half_rn(v.x), h1 = __float2half_rn(v.y);
    __half h2 = __float2half_rn(v.z), h3 = __float2half_rn(v.w);
    uint2 h;
    h.x = (uint32_t)__half_as_ushort(h0) | ((uint32_t)__half_as_ushort(h1) << 16);
    h.y = (uint32_t)__half_as_ushort(h2) | ((uint32_t)__half_as_ushort(h3) << 16);
    ((uint2*)g_a)[(size_t)r * 256 + c4] = h;
}

// ---------------- mma.sync GEMM (single-pass fp16) ----------------
// MODE 0: H = gelu(A@W1^T + b1) -> fp16.  MODE 1: Y = (A@W2^T + b2)*gate -> fp32.
template <int MODE, int KDIM>
__global__ void __launch_bounds__(256, 2) gemm_mma(
    const __half* __restrict__ Ah, const __half* __restrict__ Bh,
    const float* __restrict__ bias, int NDIM) {

    int e  = g_tile_e[blockIdx.y];
    int m0 = blockIdx.y * 128;
    if (m0 >= g_aoff[e] + g_counts[e]) return;
    int n0    = blockIdx.x * 128;
    int bbase = e * NDIM + n0;

    extern __shared__ char smem[];
    uint32_t sb  = s2u(smem);
    int tid  = threadIdx.x;
    int lane = tid & 31, wid = tid >> 5;
    int wm = wid >> 2, wn = wid & 3;   // 2x4 warp grid, warp tile 64x32

    const int NCH = KDIM / 32;

    auto load_stage = [&](int c, int st) {
        int k0 = c * 32;
        uint32_t stg = sb + st * STAGE_B;
#pragma unroll
        for (int i = 0; i < 4; i++) {               // 2 tiles * 512 chunks / 256 thr
            int ci = i * 256 + tid;
            int tile = ci >> 9, rc = ci & 511, row = rc >> 2, c16 = rc & 3;
            uint32_t dst = stg + tile * TILE_B + row * 80 + c16 * 16;
            const __half* src = (tile == 0) ? (Ah + (size_t)(m0 + row) * KDIM)
                                            : (Bh + (size_t)(bbase + row) * KDIM);
            cpasync16(dst, src + k0 + c16 * 8);
        }
        cp_commit();
    };

    int aoff = (wm * 64 + (lane & 15)) * LDSE + (lane >> 4) * 8;
    int boff = (wn * 32 + ((lane >> 4) << 3) + (lane & 7)) * LDSE + ((lane >> 3) & 1) * 8;

    float acc[4][4][4];
#pragma unroll
    for (int a = 0; a < 4; a++)
#pragma unroll
        for (int b = 0; b < 4; b++)
#pragma unroll
            for (int q = 0; q < 4; q++) acc[a][b][q] = 0.f;

    load_stage(0, 0);
    load_stage(1, 1);
    load_stage(2, 2);

    for (int c = 0; c < NCH; c++) {
        if (c + 2 < NCH)      asm volatile("cp.async.wait_group 2;" ::: "memory");
        else if (c + 1 < NCH) asm volatile("cp.async.wait_group 1;" ::: "memory");
        else                  asm volatile("cp.async.wait_group 0;" ::: "memory");
        __syncthreads();
        if (c + 3 < NCH) load_stage(c + 3, (c + 3) % NSTAGE);

        uint32_t stg = sb + (c % NSTAGE) * STAGE_B;
        uint32_t aH = stg + aoff * 2;
        uint32_t bH = stg + TILE_B + boff * 2;

#pragma unroll
        for (int kk = 0; kk < 2; kk++) {
            uint32_t k2 = kk * 32;   // 16 fp16 = 32 bytes
            uint32_t ah[4][4], bh[2][4];
#pragma unroll
            for (int g = 0; g < 2; g++) ldmx4(bh[g], bH + g * (16 * LDSE * 2) + k2);
#pragma unroll
            for (int f = 0; f < 4; f++) ldmx4(ah[f], aH + f * (16 * LDSE * 2) + k2);
#pragma unroll
            for (int mi = 0; mi < 4; mi++)
#pragma unroll
                for (int g = 0; g < 2; g++) {
                    mma16816(acc[mi][g * 2 + 0], ah[mi], &bh[g][0]);
                    mma16816(acc[mi][g * 2 + 1], ah[mi], &bh[g][2]);
                }
        }
    }

    // ---------------- epilogue ----------------
    int rbase = m0 + wm * 64 + (lane >> 2);
#pragma unroll
    for (int mi = 0; mi < 4; mi++) {
#pragma unroll
        for (int rr = 0; rr < 2; rr++) {
            int r = rbase + mi * 16 + rr * 8;
#pragma unroll
            for (int ni = 0; ni < 4; ni++) {
                int coln = n0 + wn * 32 + ni * 8 + (lane & 3) * 2;
                float v0 = acc[mi][ni][rr * 2 + 0] + bias[e * NDIM + coln];
                float v1 = acc[mi][ni][rr * 2 + 1] + bias[e * NDIM + coln + 1];
                if (MODE == 0) {
                    v0 = 0.5f * v0 * (1.f + erff(v0 * 0.70710678118654752f));
                    v1 = 0.5f * v1 * (1.f + erff(v1 * 0.70710678118654752f));
                    __half h0 = __float2half_rn(v0), h1 = __float2half_rn(v1);
                    uint32_t hp = (uint32_t)__half_as_ushort(h0) | ((uint32_t)__half_as_ushort(h1) << 16);
                    *(uint32_t*)&g_h[(size_t)r * FF_DIM + coln] = hp;
                } else {
                    float gate = g_rowgate[r];
                    float2 o = make_float2(v0 * gate, v1 * gate);
                    *(float2*)&g_y[(size_t)r * C_DIM + coln] = o;
                }
            }
        }
    }
}

// ---------------- combine ----------------
__global__ void combine_kernel(float* __restrict__ out) {
    int i = blockIdx.x * blockDim.x + threadIdx.x;   // T_TOK * 256
    if (i >= T_TOK * (C_DIM / 4)) return;
    int t = i >> 8, c4 = i & 255;
    int r0 = g_tokrow[2 * t + 0];
    int r1 = g_tokrow[2 * t + 1];
    const float4* y4 = (const float4*)g_y;
    float4 a = y4[(size_t)r0 * 256 + c4];
    float4 b = y4[(size_t)r1 * 256 + c4];
    ((float4*)out)[i] = make_float4(a.x + b.x, a.y + b.y, a.z + b.z, a.w + b.w);
}

// ---------------- host ----------------
extern "C" void kernel_launch(void* const* d_in, const int* in_sizes, int n_in,
                              void* d_out, int out_size) {
    const float* x  = (const float*)d_in[0];
    const float* rw = (const float*)d_in[1];
    const float* w1 = (const float*)d_in[2];
    const float* b1 = (const float*)d_in[3];
    const float* w2 = (const float*)d_in[4];
    const float* b2 = (const float*)d_in[5];
    float* out = (float*)d_out;

    void *pA, *pW1, *pW2, *pH;
    cudaGetSymbolAddress(&pA, g_a);
    cudaGetSymbolAddress(&pW1, g_w1);
    cudaGetSymbolAddress(&pW2, g_w2);
    cudaGetSymbolAddress(&pH, g_h);

    cudaFuncSetAttribute(gemm_mma<0, C_DIM>,  cudaFuncAttributeMaxDynamicSharedMemorySize, SMEM_TOTAL);
    cudaFuncSetAttribute(gemm_mma<1, FF_DIM>, cudaFuncAttributeMaxDynamicSharedMemorySize, SMEM_TOTAL);

    init_kernel<<<PROWS / 256, 256>>>();
    router_kernel<<<(T_TOK * 32) / 256, 256>>>(x, rw);
    scan_kernel<<<1, 1>>>();
    scatter_kernel<<<T_TOK / 256, 256>>>();
    gather_kernel<<<PROWS, 256>>>(x);

    int n4w = E_NUM * FF_DIM * C_DIM / 4;
    convert_w_kernel<<<n4w / 256, 256>>>(w1, (__half*)pW1, n4w);
    convert_w_kernel<<<n4w / 256, 256>>>(w2, (__half*)pW2, n4w);

    dim3 g1(FF_DIM / 128, MTILES);   // (32, 72)
    gemm_mma<0, C_DIM><<<g1, 256, SMEM_TOTAL>>>(
        (const __half*)pA, (const __half*)pW1, b1, FF_DIM);

    dim3 g2(C_DIM / 128, MTILES);    // (8, 72)
    gemm_mma<1, FF_DIM><<<g2, 256, SMEM_TOTAL>>>(
        (const __half*)pH, (const __half*)pW2, b2, C_DIM);

    combine_kernel<<<(T_TOK * (C_DIM / 4)) / 256, 256>>>(out);
}

// round 7
// speedup vs baseline: 6.3231x; 1.1009x over previous
#include <cuda_runtime.h>
#include <cuda_fp16.h>
#include <math.h>
#include <stdint.h>

#define T_TOK   4096
#define C_DIM   1024
#define FF_DIM  4096
#define E_NUM   8
#define PROWS   9216            // 8192 rows + per-expert pad to 128
#define MTILES  (PROWS/128)     // 72

#define KCH     64              // K columns per pipeline chunk
#define LDSE    72              // padded fp16 elems per 64-elem row (144B stride)
#define TILE_B  (128*LDSE*2)    // 18432 bytes per tile
#define STAGE_B (2*TILE_B)      // A + B = 36864
#define NSTAGE  3
#define SMEM_TOTAL (NSTAGE*STAGE_B)   // 110592 -> 2 CTAs/SM

// ---------------- scratch (static device globals; no allocation) ----------------
__device__ int   g_counts[E_NUM];
__device__ int   g_aoff[E_NUM];
__device__ int   g_cursor[E_NUM];
__device__ int   g_tile_e[MTILES];
__device__ int   g_top_idx[T_TOK * 2];
__device__ float g_top_w[T_TOK * 2];
__device__ int   g_rowtok[PROWS];
__device__ float g_rowgate[PROWS];
__device__ int   g_tokrow[T_TOK * 2];

__device__ __align__(128) __half g_a[(size_t)PROWS * C_DIM];
__device__ __align__(128) __half g_w1[(size_t)E_NUM * FF_DIM * C_DIM];
__device__ __align__(128) __half g_w2[(size_t)E_NUM * C_DIM * FF_DIM];
__device__ __align__(128) __half g_h[(size_t)PROWS * FF_DIM];
__device__ __align__(128) float  g_y[(size_t)PROWS * C_DIM];

// ---------------- PTX helpers (baseline-PTX only) ----------------
__device__ __forceinline__ uint32_t s2u(const void* p) {
    uint32_t a;
    asm("{ .reg .u64 t; cvta.to.shared.u64 t, %1; cvt.u32.u64 %0, t; }" : "=r"(a) : "l"(p));
    return a;
}
__device__ __forceinline__ void cpasync16(uint32_t dst, const void* src) {
    asm volatile("cp.async.cg.shared.global [%0], [%1], 16;" :: "r"(dst), "l"(src));
}
__device__ __forceinline__ void cp_commit() {
    asm volatile("cp.async.commit_group;" ::: "memory");
}
__device__ __forceinline__ void ldmx4(uint32_t* r, uint32_t addr) {
    asm volatile("ldmatrix.sync.aligned.m8n8.x4.shared.b16 {%0,%1,%2,%3}, [%4];"
                 : "=r"(r[0]), "=r"(r[1]), "=r"(r[2]), "=r"(r[3]) : "r"(addr));
}
__device__ __forceinline__ void mma16816(float* c, const uint32_t* a, const uint32_t* b) {
    asm volatile("mma.sync.aligned.m16n8k16.row.col.f32.f16.f16.f32 "
                 "{%0,%1,%2,%3}, {%4,%5,%6,%7}, {%8,%9}, {%0,%1,%2,%3};"
                 : "+f"(c[0]), "+f"(c[1]), "+f"(c[2]), "+f"(c[3])
                 : "r"(a[0]), "r"(a[1]), "r"(a[2]), "r"(a[3]), "r"(b[0]), "r"(b[1]));
}

// ---------------- routing ----------------
__global__ void init_kernel() {
    int i = blockIdx.x * blockDim.x + threadIdx.x;
    if (i < E_NUM) g_counts[i] = 0;
    if (i < PROWS) g_rowtok[i] = -1;
}

__global__ void router_kernel(const float* __restrict__ x, const float* __restrict__ rw) {
    int gtid = blockIdx.x * blockDim.x + threadIdx.x;
    int t = gtid >> 5, lane = threadIdx.x & 31;
    if (t >= T_TOK) return;
    const float4* xr4 = (const float4*)(x + (size_t)t * C_DIM);
    const float4* rw4 = (const float4*)rw;
    float acc[E_NUM];
#pragma unroll
    for (int e = 0; e < E_NUM; e++) acc[e] = 0.f;
    for (int c4 = lane; c4 < C_DIM / 4; c4 += 32) {
        float4 xv = xr4[c4];
#pragma unroll
        for (int e = 0; e < E_NUM; e++) {
            float4 wv = rw4[e * (C_DIM / 4) + c4];
            acc[e] += xv.x * wv.x + xv.y * wv.y + xv.z * wv.z + xv.w * wv.w;
        }
    }
#pragma unroll
    for (int e = 0; e < E_NUM; e++)
#pragma unroll
        for (int o = 16; o; o >>= 1) acc[e] += __shfl_xor_sync(0xFFFFFFFFu, acc[e], o);
    if (lane == 0) {
        float m = acc[0];
#pragma unroll
        for (int e = 1; e < E_NUM; e++) m = fmaxf(m, acc[e]);
        float p[E_NUM], Z = 0.f;
#pragma unroll
        for (int e = 0; e < E_NUM; e++) { p[e] = expf(acc[e] - m); Z += p[e]; }
#pragma unroll
        for (int e = 0; e < E_NUM; e++) p[e] /= Z;
        int i0 = 0;
#pragma unroll
        for (int e = 1; e < E_NUM; e++) if (p[e] > p[i0]) i0 = e;
        int i1 = (i0 == 0) ? 1 : 0;
#pragma unroll
        for (int e = 0; e < E_NUM; e++) if (e != i0 && p[e] > p[i1]) i1 = e;
        float s = p[i0] + p[i1] + 1e-9f;
        g_top_idx[2 * t + 0] = i0; g_top_w[2 * t + 0] = p[i0] / s;
        g_top_idx[2 * t + 1] = i1; g_top_w[2 * t + 1] = p[i1] / s;
        atomicAdd(&g_counts[i0], 1);
        atomicAdd(&g_counts[i1], 1);
    }
}

__global__ void scan_kernel() {
    if (threadIdx.x == 0) {
        int o = 0;
        for (int e = 0; e < E_NUM; e++) {
            g_aoff[e] = o; g_cursor[e] = o;
            int a = (g_counts[e] + 127) & ~127;
            for (int t = o / 128; t < (o + a) / 128; t++) g_tile_e[t] = e;
            o += a;
        }
        for (int t = o / 128; t < MTILES; t++) g_tile_e[t] = E_NUM - 1;
    }
}

__global__ void scatter_kernel() {
    int t = blockIdx.x * blockDim.x + threadIdx.x;
    if (t >= T_TOK) return;
#pragma unroll
    for (int k = 0; k < 2; k++) {
        int e = g_top_idx[2 * t + k];
        int row = atomicAdd(&g_cursor[e], 1);
        g_rowtok[row] = t;
        g_rowgate[row] = g_top_w[2 * t + k];
        g_tokrow[2 * t + k] = row;
    }
}

// ---------------- fp16 conversions ----------------
__global__ void convert_w_kernel(const float* __restrict__ w, __half* __restrict__ hi, int n4) {
    int i = blockIdx.x * blockDim.x + threadIdx.x;
    if (i >= n4) return;
    float4 v = ((const float4*)w)[i];
    __half h0 = __float2half_rn(v.x), h1 = __float2half_rn(v.y);
    __half h2 = __float2half_rn(v.z), h3 = __float2half_rn(v.w);
    uint2 h;
    h.x = (uint32_t)__half_as_ushort(h0) | ((uint32_t)__half_as_ushort(h1) << 16);
    h.y = (uint32_t)__half_as_ushort(h2) | ((uint32_t)__half_as_ushort(h3) << 16);
    ((uint2*)hi)[i] = h;
}

__global__ void gather_kernel(const float* __restrict__ x) {
    int idx = blockIdx.x * blockDim.x + threadIdx.x;   // over PROWS * 256
    int r = idx >> 8, c4 = idx & 255;
    int t = g_rowtok[r];
    float4 v = make_float4(0.f, 0.f, 0.f, 0.f);
    if (t >= 0) v = ((const float4*)x)[(size_t)t * 256 + c4];
    __half h0 = __float2half_rn(v.x), h1 = __float2half_rn(v.y);
    __half h2 = __float2half_rn(v.z), h3 = __float2half_rn(v.w);
    uint2 h;
    h.x = (uint32_t)__half_as_ushort(h0) | ((uint32_t)__half_as_ushort(h1) << 16);
    h.y = (uint32_t)__half_as_ushort(h2) | ((uint32_t)__half_as_ushort(h3) << 16);
    ((uint2*)g_a)[(size_t)r * 256 + c4] = h;
}

// ---------------- mma.sync GEMM (single-pass fp16, K-chunk 64) ----------------
// MODE 0: H = gelu(A@W1^T + b1) -> fp16.  MODE 1: Y = (A@W2^T + b2)*gate -> fp32.
template <int MODE, int KDIM>
__global__ void __launch_bounds__(256, 2) gemm_mma(
    const __half* __restrict__ Ah, const __half* __restrict__ Bh,
    const float* __restrict__ bias, int NDIM) {

    int e  = g_tile_e[blockIdx.y];
    int m0 = blockIdx.y * 128;
    if (m0 >= g_aoff[e] + g_counts[e]) return;
    int n0    = blockIdx.x * 128;
    int bbase = e * NDIM + n0;

    extern __shared__ char smem[];
    uint32_t sb  = s2u(smem);
    int tid  = threadIdx.x;
    int lane = tid & 31, wid = tid >> 5;
    int wm = wid >> 2, wn = wid & 3;   // 2x4 warp grid, warp tile 64x32

    const int NCH = KDIM / KCH;

    auto load_stage = [&](int c, int st) {
        int k0 = c * KCH;
        uint32_t stg = sb + st * STAGE_B;
#pragma unroll
        for (int i = 0; i < 8; i++) {               // 2 tiles * 1024 chunks / 256 thr
            int ci = i * 256 + tid;
            int tile = ci >> 10, rc = ci & 1023, row = rc >> 3, c16 = rc & 7;
            uint32_t dst = stg + tile * TILE_B + row * (LDSE * 2) + c16 * 16;
            const __half* src = (tile == 0) ? (Ah + (size_t)(m0 + row) * KDIM)
                                            : (Bh + (size_t)(bbase + row) * KDIM);
            cpasync16(dst, src + k0 + c16 * 8);
        }
        cp_commit();
    };

    int aoff = (wm * 64 + (lane & 15)) * LDSE + (lane >> 4) * 8;
    int boff = (wn * 32 + ((lane >> 4) << 3) + (lane & 7)) * LDSE + ((lane >> 3) & 1) * 8;

    float acc[4][4][4];
#pragma unroll
    for (int a = 0; a < 4; a++)
#pragma unroll
        for (int b = 0; b < 4; b++)
#pragma unroll
            for (int q = 0; q < 4; q++) acc[a][b][q] = 0.f;

    load_stage(0, 0);
    load_stage(1, 1);

    for (int c = 0; c < NCH; c++) {
        if (c + 1 < NCH) asm volatile("cp.async.wait_group 1;" ::: "memory");
        else             asm volatile("cp.async.wait_group 0;" ::: "memory");
        __syncthreads();
        if (c + 2 < NCH) load_stage(c + 2, (c + 2) % NSTAGE);

        uint32_t stg = sb + (c % NSTAGE) * STAGE_B;
        uint32_t aH = stg + aoff * 2;
        uint32_t bH = stg + TILE_B + boff * 2;

#pragma unroll
        for (int kk = 0; kk < 4; kk++) {
            uint32_t k2 = kk * 32;   // 16 fp16 = 32 bytes
            uint32_t ah[4][4], bh[2][4];
#pragma unroll
            for (int g = 0; g < 2; g++) ldmx4(bh[g], bH + g * (16 * LDSE * 2) + k2);
#pragma unroll
            for (int f = 0; f < 4; f++) ldmx4(ah[f], aH + f * (16 * LDSE * 2) + k2);
#pragma unroll
            for (int mi = 0; mi < 4; mi++)
#pragma unroll
                for (int g = 0; g < 2; g++) {
                    mma16816(acc[mi][g * 2 + 0], ah[mi], &bh[g][0]);
                    mma16816(acc[mi][g * 2 + 1], ah[mi], &bh[g][2]);
                }
        }
    }

    // ---------------- epilogue ----------------
    int rbase = m0 + wm * 64 + (lane >> 2);
#pragma unroll
    for (int mi = 0; mi < 4; mi++) {
#pragma unroll
        for (int rr = 0; rr < 2; rr++) {
            int r = rbase + mi * 16 + rr * 8;
#pragma unroll
            for (int ni = 0; ni < 4; ni++) {
                int coln = n0 + wn * 32 + ni * 8 + (lane & 3) * 2;
                float v0 = acc[mi][ni][rr * 2 + 0] + bias[e * NDIM + coln];
                float v1 = acc[mi][ni][rr * 2 + 1] + bias[e * NDIM + coln + 1];
                if (MODE == 0) {
                    v0 = 0.5f * v0 * (1.f + erff(v0 * 0.70710678118654752f));
                    v1 = 0.5f * v1 * (1.f + erff(v1 * 0.70710678118654752f));
                    __half h0 = __float2half_rn(v0), h1 = __float2half_rn(v1);
                    uint32_t hp = (uint32_t)__half_as_ushort(h0) | ((uint32_t)__half_as_ushort(h1) << 16);
                    *(uint32_t*)&g_h[(size_t)r * FF_DIM + coln] = hp;
                } else {
                    float gate = g_rowgate[r];
                    float2 o = make_float2(v0 * gate, v1 * gate);
                    *(float2*)&g_y[(size_t)r * C_DIM + coln] = o;
                }
            }
        }
    }
}

// ---------------- combine ----------------
__global__ void combine_kernel(float* __restrict__ out) {
    int i = blockIdx.x * blockDim.x + threadIdx.x;   // T_TOK * 256
    if (i >= T_TOK * (C_DIM / 4)) return;
    int t = i >> 8, c4 = i & 255;
    int r0 = g_tokrow[2 * t + 0];
    int r1 = g_tokrow[2 * t + 1];
    const float4* y4 = (const float4*)g_y;
    float4 a = y4[(size_t)r0 * 256 + c4];
    float4 b = y4[(size_t)r1 * 256 + c4];
    ((float4*)out)[i] = make_float4(a.x + b.x, a.y + b.y, a.z + b.z, a.w + b.w);
}

// ---------------- host ----------------
extern "C" void kernel_launch(void* const* d_in, const int* in_sizes, int n_in,
                              void* d_out, int out_size) {
    const float* x  = (const float*)d_in[0];
    const float* rw = (const float*)d_in[1];
    const float* w1 = (const float*)d_in[2];
    const float* b1 = (const float*)d_in[3];
    const float* w2 = (const float*)d_in[4];
    const float* b2 = (const float*)d_in[5];
    float* out = (float*)d_out;

    void *pA, *pW1, *pW2, *pH;
    cudaGetSymbolAddress(&pA, g_a);
    cudaGetSymbolAddress(&pW1, g_w1);
    cudaGetSymbolAddress(&pW2, g_w2);
    cudaGetSymbolAddress(&pH, g_h);

    cudaFuncSetAttribute(gemm_mma<0, C_DIM>,  cudaFuncAttributeMaxDynamicSharedMemorySize, SMEM_TOTAL);
    cudaFuncSetAttribute(gemm_mma<1, FF_DIM>, cudaFuncAttributeMaxDynamicSharedMemorySize, SMEM_TOTAL);

    init_kernel<<<PROWS / 256, 256>>>();
    router_kernel<<<(T_TOK * 32) / 256, 256>>>(x, rw);
    scan_kernel<<<1, 1>>>();
    scatter_kernel<<<T_TOK / 256, 256>>>();
    gather_kernel<<<PROWS, 256>>>(x);

    int n4w = E_NUM * FF_DIM * C_DIM / 4;
    convert_w_kernel<<<n4w / 256, 256>>>(w1, (__half*)pW1, n4w);
    convert_w_kernel<<<n4w / 256, 256>>>(w2, (__half*)pW2, n4w);

    dim3 g1(FF_DIM / 128, MTILES);   // (32, 72)
    gemm_mma<0, C_DIM><<<g1, 256, SMEM_TOTAL>>>(
        (const __half*)pA, (const __half*)pW1, b1, FF_DIM);

    dim3 g2(C_DIM / 128, MTILES);    // (8, 72)
    gemm_mma<1, FF_DIM><<<g2, 256, SMEM_TOTAL>>>(
        (const __half*)pH, (const __half*)pW2, b2, C_DIM);

    combine_kernel<<<(T_TOK * (C_DIM / 4)) / 256, 256>>>(out);
}